// round 5
// baseline (speedup 1.0000x reference)
#include <cuda_runtime.h>
#include <cuda_bf16.h>
#include <cstdint>

#define CIN   64
#define COUT  64
#define DD    16
#define HH    64
#define WW    64
#define PTOT  (DD*HH*WW)      // 65536
#define C3    21
#define LOG2E 1.4426950408889634f

// scratch: rows 0-63 = q, 64-127 = k, 128-191 = v
__device__ float  g_qkv[192 * PTOT];
// pre-transposed, pre-duplicated weights: [ci][c] -> {w,w}, 16B aligned for cp.async
__device__ __align__(16) float2 g_wt2[64 * 192];

__device__ __forceinline__ void fma2(unsigned long long& d,
                                     unsigned long long a,
                                     unsigned long long b) {
    asm("fma.rn.f32x2 %0, %1, %2, %0;" : "+l"(d) : "l"(a), "l"(b));
}

__device__ __forceinline__ float ex2(float x) {
    float r;
    asm("ex2.approx.ftz.f32 %0, %1;" : "=f"(r) : "f"(x));
    return r;
}

__device__ __forceinline__ void cpasync16(unsigned int dst_smem, const void* src) {
    asm volatile("cp.async.cg.shared.global [%0], [%1], 16;\n"
                 :: "r"(dst_smem), "l"(src));
}
__device__ __forceinline__ void cp_commit() {
    asm volatile("cp.async.commit_group;\n" ::: "memory");
}
template<int N>
__device__ __forceinline__ void cp_wait() {
    asm volatile("cp.async.wait_group %0;\n" :: "n"(N) : "memory");
}

// ---------------------------------------------------------------------------
// Kernel 0: one-shot weight transpose + duplicate (12288 elements)
// ---------------------------------------------------------------------------
__global__ void prep_kernel(const float* __restrict__ wq,
                            const float* __restrict__ wk,
                            const float* __restrict__ wv) {
    int j = blockIdx.x * 512 + threadIdx.x;
    if (j < 64 * 192) {
        int ci = j / 192, c = j % 192;
        float w;
        if (c < 64)       w = wq[c * 64 + ci];
        else if (c < 128) w = wk[(c - 64) * 64 + ci];
        else              w = wv[(c - 128) * 64 + ci];
        g_wt2[j] = make_float2(w, w);
    }
}

// ---------------------------------------------------------------------------
// Kernel 1: qkv = W(192x64) @ x(64x65536)
// 128 blocks (one wave), 512 threads, 4 tiles of 128 positions each.
// Weights staged ONCE per block; x tiles double-buffered via cp.async so
// tile t+1 loads overlap tile t compute. Position-paired f32x2 FMA:
//   acc{p,p+1} += {w,w} * {x_p,x_p+1}
// ---------------------------------------------------------------------------
#define QTILE   128
#define NTILES  4

__global__ void __launch_bounds__(512, 1)
qkv_kernel(const float* __restrict__ x) {
    extern __shared__ char smem[];
    float2* wt2 = (float2*)smem;                              // [64][192] 96KB
    float*  xs  = (float*)(smem + 64 * 192 * sizeof(float2)); // [2][64][128] 64KB

    const int tid = threadIdx.x;
    const int p0  = blockIdx.x * (QTILE * NTILES);

    const unsigned int wt2_s = (unsigned int)__cvta_generic_to_shared(wt2);
    const unsigned int xs_s  = (unsigned int)__cvta_generic_to_shared(xs);

    // group 0: weights (96KB = 6144 x 16B, 12 per thread)
#pragma unroll
    for (int it = 0; it < 12; it++) {
        int j = it * 512 + tid;
        cpasync16(wt2_s + j * 16, (const char*)g_wt2 + j * 16);
    }
    cp_commit();

    // prefetch x tile 0 (32KB = 2048 x 16B, 4 per thread)
#pragma unroll
    for (int it = 0; it < 4; it++) {
        int j  = it * 512 + tid;
        int ci = j >> 5, f4 = j & 31;               // 32 float4 per ci-row
        cpasync16(xs_s + (ci * 128 + f4 * 4) * 4,
                  x + ci * PTOT + p0 + f4 * 4);
    }
    cp_commit();

    const int cg   = tid >> 5;   // 0..15 : 12-channel group (warp-uniform)
    const int lane = tid & 31;   // 4 positions: lane*4 .. lane*4+3

    for (int t = 0; t < NTILES; t++) {
        // prefetch next tile into the other buffer
        if (t + 1 < NTILES) {
            unsigned int dst = xs_s + ((t + 1) & 1) * (64 * 128 * 4);
            const float* src = x + p0 + (t + 1) * QTILE;
#pragma unroll
            for (int it = 0; it < 4; it++) {
                int j  = it * 512 + tid;
                int ci = j >> 5, f4 = j & 31;
                cpasync16(dst + (ci * 128 + f4 * 4) * 4,
                          src + ci * PTOT + f4 * 4);
            }
            cp_commit();
            cp_wait<1>();   // tile t (and weights) complete
        } else {
            cp_wait<0>();
        }
        __syncthreads();

        const float* xbuf = xs + (t & 1) * (64 * 128);
        unsigned long long acc[12][2] = {};

#pragma unroll 8
        for (int ci = 0; ci < 64; ci++) {
            const ulonglong2* wr = (const ulonglong2*)(wt2 + ci * 192 + cg * 12);
            ulonglong2 wa = wr[0], wb = wr[1], wc = wr[2];
            ulonglong2 wd = wr[3], we = wr[4], wf = wr[5];
            unsigned long long wp[12] = {wa.x, wa.y, wb.x, wb.y, wc.x, wc.y,
                                         wd.x, wd.y, we.x, we.y, wf.x, wf.y};
            ulonglong2 xp = *(const ulonglong2*)(xbuf + ci * 128 + lane * 4);

#pragma unroll
            for (int ch = 0; ch < 12; ch++) {
                fma2(acc[ch][0], wp[ch], xp.x);
                fma2(acc[ch][1], wp[ch], xp.y);
            }
        }

        const int pbase = p0 + t * QTILE + lane * 4;
#pragma unroll
        for (int ch = 0; ch < 12; ch++) {
            int c = cg * 12 + ch;
            ulonglong2 v;
            v.x = acc[ch][0];
            v.y = acc[ch][1];
            *(ulonglong2*)(g_qkv + c * PTOT + pbase) = v;
        }
        __syncthreads();   // protect buffer (t&1) before next prefetch cycle
    }
}

// ---------------------------------------------------------------------------
// Kernel 2: windowed softmax attention.
// Block: (64 w, 8 h), 2 channels per block. k,v staged interleaved {k,v}
// with 1-column zero halo on both w edges (rows of 66) -> no per-tap
// predication; taps are LDS.64 + FFMA + MUFU.EX2 + FADD + FFMA.
// No max subtraction (|score| << 126 in log2 domain).
// ---------------------------------------------------------------------------
#define ROWLEN 66

template<int A>
__device__ __forceinline__ void tap_loop(const float2* __restrict__ skv,
                                         int ty, int w, float qs,
                                         float qb0, float qb1, float qb2,
                                         float& den, float& num) {
#pragma unroll
    for (int kd = 0; kd < 3; kd++) {
#pragma unroll
        for (int kh = 0; kh < 3; kh++) {
            const float2* row = skv + (kd * 10 + (ty + kh)) * ROWLEN + w;
#pragma unroll
            for (int kw = 0; kw < 3; kw++) {
                float2 kv = row[kw];
                float qb = (A == 0) ? (kd == 0 ? qb0 : kd == 1 ? qb1 : qb2)
                         : (A == 1) ? (kh == 0 ? qb0 : kh == 1 ? qb1 : qb2)
                                    : (kw == 0 ? qb0 : kw == 1 ? qb1 : qb2);
                float e = ex2(fmaf(qs, kv.x, qb));
                den += e;
                num = fmaf(e, kv.y, num);
            }
        }
    }
}

__global__ void __launch_bounds__(512)
attn_kernel(const float* __restrict__ rel_d,
            const float* __restrict__ rel_h,
            const float* __restrict__ rel_w,
            float* __restrict__ out) {
    __shared__ float2 skv[2][3][10][ROWLEN];   // {k,v}, 31680 B

    const int w   = threadIdx.x;
    const int ty  = threadIdx.y;
    const int tid = ty * 64 + w;
    const int d   = blockIdx.x >> 3;
    const int h0  = (blockIdx.x & 7) * 8;
    const int c0  = blockIdx.y * 2;

    // stage k,v for both channels: 3 d-planes x 10 h-rows x 66 w (halo cols 0)
    {
        float2* flat = &skv[0][0][0][0];
        const int TOT = 2 * 3 * 10 * ROWLEN;   // 3960
        for (int i = tid; i < TOT; i += 512) {
            int ci  = i / (3 * 10 * ROWLEN);
            int r   = i - ci * (3 * 10 * ROWLEN);
            int ndi = r / (10 * ROWLEN);
            int r2  = r - ndi * (10 * ROWLEN);
            int nhi = r2 / ROWLEN;
            int wi  = r2 - nhi * ROWLEN;
            int nd = d + ndi - 1;
            int nh = h0 + nhi - 1;
            int nw = wi - 1;
            float kk = 0.f, vv = 0.f;
            if ((unsigned)nd < (unsigned)DD && (unsigned)nh < (unsigned)HH &&
                (unsigned)nw < (unsigned)WW) {
                int g = (nd << 12) + (nh << 6) + nw;
                kk = g_qkv[(64  + c0 + ci) * PTOT + g];
                vv = g_qkv[(128 + c0 + ci) * PTOT + g];
            }
            flat[i] = make_float2(kk, vv);
        }
    }
    __syncthreads();

    const int h = h0 + ty;
    const int p = (d << 12) + (h << 6) + w;

#pragma unroll
    for (int ci = 0; ci < 2; ci++) {
        const int c = c0 + ci;
        const float q  = g_qkv[c * PTOT + p];
        const float qs = q * LOG2E;

        int axis;
        const float* bp;
        if (c < C3)          { axis = 0; bp = rel_d + c * 3; }
        else if (c < 2 * C3) { axis = 1; bp = rel_h + (c - C3) * 3; }
        else                 { axis = 2; bp = rel_w + (c - 2 * C3) * 3; }
        const float qb0 = qs * bp[0];
        const float qb1 = qs * bp[1];
        const float qb2 = qs * bp[2];

        float den = 0.f, num = 0.f;
        const float2* skv_c = &skv[ci][0][0][0];
        if (axis == 0)      tap_loop<0>(skv_c, ty, w, qs, qb0, qb1, qb2, den, num);
        else if (axis == 1) tap_loop<1>(skv_c, ty, w, qs, qb0, qb1, qb2, den, num);
        else                tap_loop<2>(skv_c, ty, w, qs, qb0, qb1, qb2, den, num);

        out[c * PTOT + p] = __fdividef(num, den);
    }
}

// ---------------------------------------------------------------------------
extern "C" void kernel_launch(void* const* d_in, const int* in_sizes, int n_in,
                              void* d_out, int out_size) {
    const float* x     = (const float*)d_in[0];
    const float* wq    = (const float*)d_in[1];
    const float* wk    = (const float*)d_in[2];
    const float* wv    = (const float*)d_in[3];
    const float* rel_d = (const float*)d_in[4];
    const float* rel_h = (const float*)d_in[5];
    const float* rel_w = (const float*)d_in[6];
    float* out = (float*)d_out;

    prep_kernel<<<24, 512>>>(wq, wk, wv);

    const int smem_bytes = 64 * 192 * sizeof(float2)        // weights  96KB
                         + 2 * 64 * 128 * sizeof(float);    // x dbl-buf 64KB
    cudaFuncSetAttribute(qkv_kernel, cudaFuncAttributeMaxDynamicSharedMemorySize,
                         smem_bytes);
    qkv_kernel<<<PTOT / (QTILE * NTILES), 512, smem_bytes>>>(x);

    dim3 grid(DD * (HH / 8), COUT / 2);   // (128, 32)
    dim3 block(WW, 8);
    attn_kernel<<<grid, block>>>(rel_d, rel_h, rel_w, out);
}

// round 7
// speedup vs baseline: 1.6277x; 1.6277x over previous
#include <cuda_runtime.h>
#include <cuda_bf16.h>
#include <cstdint>

#define CIN   64
#define COUT  64
#define DD    16
#define HH    64
#define WW    64
#define PTOT  (DD*HH*WW)      // 65536
#define C3    21
#define LOG2E 1.4426950408889634f

// scratch: rows 0-63 = q, 64-127 = k, 128-191 = v
__device__ float  g_qkv[192 * PTOT];
// pre-transposed, pre-duplicated weights: [ci][c] -> {w,w}
__device__ __align__(16) float2 g_wt2[64 * 192];

__device__ __forceinline__ void fma2(unsigned long long& d,
                                     unsigned long long a,
                                     unsigned long long b) {
    asm("fma.rn.f32x2 %0, %1, %2, %0;" : "+l"(d) : "l"(a), "l"(b));
}

__device__ __forceinline__ float ex2(float x) {
    float r;
    asm("ex2.approx.ftz.f32 %0, %1;" : "=f"(r) : "f"(x));
    return r;
}

// ---------------------------------------------------------------------------
// Kernel 0: one-shot weight transpose + duplicate (coalesced reads,
// scattered fire-and-forget writes)
// ---------------------------------------------------------------------------
__global__ void prep_kernel(const float* __restrict__ wq,
                            const float* __restrict__ wk,
                            const float* __restrict__ wv) {
    int j = blockIdx.x * 512 + threadIdx.x;
    if (j < 64 * 192) {
        int ci = j & 63;          // fastest -> coalesced source reads
        int c  = j >> 6;
        float w;
        if (c < 64)       w = wq[c * 64 + ci];
        else if (c < 128) w = wk[(c - 64) * 64 + ci];
        else              w = wv[(c - 128) * 64 + ci];
        g_wt2[ci * 192 + c] = make_float2(w, w);
    }
}

// ---------------------------------------------------------------------------
// Kernel 1: qkv = W(192x64) @ x(64x65536)
// Grid (512 position-tiles, 2 channel-halves). 256 threads/block,
// 96 channels x 128 positions per block. smem = 48KB weights + 32KB x
// = 80KB -> occupancy 2 (staging of one block overlaps compute of the other).
// Position-paired f32x2: acc{p,p+1} += {w,w} * {x_p,x_p+1}.
// ---------------------------------------------------------------------------
__global__ void __launch_bounds__(256, 2)
qkv_kernel(const float* __restrict__ x) {
    extern __shared__ char smem[];
    float2* wt2 = (float2*)smem;                             // [64][96]  48KB
    float*  xs  = (float*)(smem + 64 * 96 * sizeof(float2)); // [64][128] 32KB

    const int tid = threadIdx.x;
    const int p0  = blockIdx.x * 128;
    const int c0  = blockIdx.y * 96;

    // stage weights for this channel half: 64 rows x 48 float4, coalesced
    {
        const float4* src = (const float4*)g_wt2;   // row stride 96 float4
        float4* dst = (float4*)wt2;                 // row stride 48 float4
        const int c4 = c0 >> 1;                     // float4 col offset
#pragma unroll
        for (int it = 0; it < 12; it++) {
            int j    = it * 256 + tid;
            int ci   = j / 48;
            int col4 = j - ci * 48;
            dst[ci * 48 + col4] = src[ci * 96 + c4 + col4];
        }
    }
    // stage x tile: 64 rows x 32 float4
    {
        float4* dst = (float4*)xs;
#pragma unroll
        for (int it = 0; it < 8; it++) {
            int j  = it * 256 + tid;
            int ci = j >> 5, f4 = j & 31;
            dst[ci * 32 + f4] = *(const float4*)(x + ci * PTOT + p0 + f4 * 4);
        }
    }
    __syncthreads();

    const int cg   = tid >> 5;   // 0..7 : 12-channel group (warp-uniform)
    const int lane = tid & 31;   // 4 positions: lane*4 .. lane*4+3

    unsigned long long acc[12][2] = {};

#pragma unroll 8
    for (int ci = 0; ci < 64; ci++) {
        const ulonglong2* wr = (const ulonglong2*)(wt2 + ci * 96 + cg * 12);
        ulonglong2 wa = wr[0], wb = wr[1], wc = wr[2];
        ulonglong2 wd = wr[3], we = wr[4], wf = wr[5];
        unsigned long long wp[12] = {wa.x, wa.y, wb.x, wb.y, wc.x, wc.y,
                                     wd.x, wd.y, we.x, we.y, wf.x, wf.y};
        ulonglong2 xp = *(const ulonglong2*)(xs + ci * 128 + lane * 4);

#pragma unroll
        for (int ch = 0; ch < 12; ch++) {
            fma2(acc[ch][0], wp[ch], xp.x);
            fma2(acc[ch][1], wp[ch], xp.y);
        }
    }

    const int pbase = p0 + lane * 4;
#pragma unroll
    for (int ch = 0; ch < 12; ch++) {
        int c = c0 + cg * 12 + ch;
        ulonglong2 v;
        v.x = acc[ch][0];
        v.y = acc[ch][1];
        *(ulonglong2*)(g_qkv + c * PTOT + pbase) = v;
    }
}

// ---------------------------------------------------------------------------
// Kernel 2: windowed softmax attention.
// Block: (64 w, 8 h), 2 channels per block. k,v staged interleaved {k,v}
// with 1-column zero halo on both w edges (rows of 66) -> no per-tap
// predication; taps are LDS.64 + FFMA + MUFU.EX2 + FADD + FFMA.
// No max subtraction (|score| << 126 in log2 domain).
// ---------------------------------------------------------------------------
#define ROWLEN 66

template<int A>
__device__ __forceinline__ void tap_loop(const float2* __restrict__ skv,
                                         int ty, int w, float qs,
                                         float qb0, float qb1, float qb2,
                                         float& den, float& num) {
#pragma unroll
    for (int kd = 0; kd < 3; kd++) {
#pragma unroll
        for (int kh = 0; kh < 3; kh++) {
            const float2* row = skv + (kd * 10 + (ty + kh)) * ROWLEN + w;
#pragma unroll
            for (int kw = 0; kw < 3; kw++) {
                float2 kv = row[kw];
                float qb = (A == 0) ? (kd == 0 ? qb0 : kd == 1 ? qb1 : qb2)
                         : (A == 1) ? (kh == 0 ? qb0 : kh == 1 ? qb1 : qb2)
                                    : (kw == 0 ? qb0 : kw == 1 ? qb1 : qb2);
                float e = ex2(fmaf(qs, kv.x, qb));
                den += e;
                num = fmaf(e, kv.y, num);
            }
        }
    }
}

__global__ void __launch_bounds__(512)
attn_kernel(const float* __restrict__ rel_d,
            const float* __restrict__ rel_h,
            const float* __restrict__ rel_w,
            float* __restrict__ out) {
    __shared__ float2 skv[2][3][10][ROWLEN];   // {k,v}, 31680 B

    const int w   = threadIdx.x;
    const int ty  = threadIdx.y;
    const int tid = ty * 64 + w;
    const int d   = blockIdx.x >> 3;
    const int h0  = (blockIdx.x & 7) * 8;
    const int c0  = blockIdx.y * 2;

    // stage k,v for both channels: 3 d-planes x 10 h-rows x 66 w (halo cols 0)
    {
        float2* flat = &skv[0][0][0][0];
        const int TOT = 2 * 3 * 10 * ROWLEN;   // 3960
        for (int i = tid; i < TOT; i += 512) {
            int ci  = i / (3 * 10 * ROWLEN);
            int r   = i - ci * (3 * 10 * ROWLEN);
            int ndi = r / (10 * ROWLEN);
            int r2  = r - ndi * (10 * ROWLEN);
            int nhi = r2 / ROWLEN;
            int wi  = r2 - nhi * ROWLEN;
            int nd = d + ndi - 1;
            int nh = h0 + nhi - 1;
            int nw = wi - 1;
            float kk = 0.f, vv = 0.f;
            if ((unsigned)nd < (unsigned)DD && (unsigned)nh < (unsigned)HH &&
                (unsigned)nw < (unsigned)WW) {
                int g = (nd << 12) + (nh << 6) + nw;
                kk = g_qkv[(64  + c0 + ci) * PTOT + g];
                vv = g_qkv[(128 + c0 + ci) * PTOT + g];
            }
            flat[i] = make_float2(kk, vv);
        }
    }
    __syncthreads();

    const int h = h0 + ty;
    const int p = (d << 12) + (h << 6) + w;

#pragma unroll
    for (int ci = 0; ci < 2; ci++) {
        const int c = c0 + ci;
        const float q  = g_qkv[c * PTOT + p];
        const float qs = q * LOG2E;

        int axis;
        const float* bp;
        if (c < C3)          { axis = 0; bp = rel_d + c * 3; }
        else if (c < 2 * C3) { axis = 1; bp = rel_h + (c - C3) * 3; }
        else                 { axis = 2; bp = rel_w + (c - 2 * C3) * 3; }
        const float qb0 = qs * bp[0];
        const float qb1 = qs * bp[1];
        const float qb2 = qs * bp[2];

        float den = 0.f, num = 0.f;
        const float2* skv_c = &skv[ci][0][0][0];
        if (axis == 0)      tap_loop<0>(skv_c, ty, w, qs, qb0, qb1, qb2, den, num);
        else if (axis == 1) tap_loop<1>(skv_c, ty, w, qs, qb0, qb1, qb2, den, num);
        else                tap_loop<2>(skv_c, ty, w, qs, qb0, qb1, qb2, den, num);

        out[c * PTOT + p] = __fdividef(num, den);
    }
}

// ---------------------------------------------------------------------------
extern "C" void kernel_launch(void* const* d_in, const int* in_sizes, int n_in,
                              void* d_out, int out_size) {
    const float* x     = (const float*)d_in[0];
    const float* wq    = (const float*)d_in[1];
    const float* wk    = (const float*)d_in[2];
    const float* wv    = (const float*)d_in[3];
    const float* rel_d = (const float*)d_in[4];
    const float* rel_h = (const float*)d_in[5];
    const float* rel_w = (const float*)d_in[6];
    float* out = (float*)d_out;

    prep_kernel<<<24, 512>>>(wq, wk, wv);

    const int smem_bytes = 64 * 96 * sizeof(float2)      // weights 48KB
                         + 64 * 128 * sizeof(float);     // x tile  32KB
    cudaFuncSetAttribute(qkv_kernel, cudaFuncAttributeMaxDynamicSharedMemorySize,
                         smem_bytes);
    dim3 qgrid(PTOT / 128, 2);
    qkv_kernel<<<qgrid, 256, smem_bytes>>>(x);

    dim3 grid(DD * (HH / 8), COUT / 2);   // (128, 32)
    dim3 block(WW, 8);
    attn_kernel<<<grid, block>>>(rel_d, rel_h, rel_w, out);
}